// round 11
// baseline (speedup 1.0000x reference)
#include <cuda_runtime.h>
#include <cstdint>

#define VOCAB 256
#define D 512
#define A 64
#define BB 8
#define LL 2048
#define LN_EPS 1e-5f

// ---------------- scratch (device globals; no allocations) ----------------
__device__ float4 g_h4[VOCAB * 128];       // h row-major: [v][d/4]
__device__ float g_q[VOCAB * A];
__device__ float g_kT[A * VOCAB];
__device__ float g_gate[VOCAB];
__device__ float g_logit[VOCAB * VOCAB];
__device__ float g_vprob[VOCAB * VOCAB];
__device__ float g_score[VOCAB * VOCAB];
__device__ float g_cnt[BB * VOCAB];

// ---------------- reduction helpers ----------------
__device__ __forceinline__ float warpSum(float v) {
    #pragma unroll
    for (int o = 16; o > 0; o >>= 1) v += __shfl_xor_sync(0xFFFFFFFFu, v, o);
    return v;
}
__device__ __forceinline__ float warpMax(float v) {
    #pragma unroll
    for (int o = 16; o > 0; o >>= 1) v = fmaxf(v, __shfl_xor_sync(0xFFFFFFFFu, v, o));
    return v;
}
// reduce two values with 5 SHFL: lanes 0-15 end with sum(a), lanes 16-31 sum(b)
__device__ __forceinline__ float warpSumDual(float a, float b, int l) {
    float x = (l < 16) ? a : b;
    float y = __shfl_xor_sync(0xFFFFFFFFu, (l < 16) ? b : a, 16);
    x += y;
    #pragma unroll
    for (int o = 8; o > 0; o >>= 1) x += __shfl_xor_sync(0xFFFFFFFFu, x, o);
    return x;
}
__device__ __forceinline__ float blockSum256(float v, float* sh) {
    int w = threadIdx.x >> 5, l = threadIdx.x & 31;
    v = warpSum(v);
    if (l == 0) sh[w] = v;
    __syncthreads();
    if (w == 0) {
        float x = (l < 8) ? sh[l] : 0.f;
        x = warpSum(x);
        if (l == 0) sh[0] = x;
    }
    __syncthreads();
    float r = sh[0];
    __syncthreads();
    return r;
}
__device__ __forceinline__ float blockMax256(float v, float* sh) {
    int w = threadIdx.x >> 5, l = threadIdx.x & 31;
    v = warpMax(v);
    if (l == 0) sh[w] = v;
    __syncthreads();
    if (w == 0) {
        float x = (l < 8) ? sh[l] : -1e30f;
        x = warpMax(x);
        if (l == 0) sh[0] = x;
    }
    __syncthreads();
    float r = sh[0];
    __syncthreads();
    return r;
}

// ---------------- k_hn: histogram (blocks 0-7) + LN once (blocks 8-39) ----
__global__ void __launch_bounds__(256)
k_hn(const int* __restrict__ tokens, const int* __restrict__ plen,
     const float* __restrict__ E,
     const float* __restrict__ eg, const float* __restrict__ eb,
     const float* __restrict__ fg, const float* __restrict__ fb) {
    int tid = threadIdx.x, w = tid >> 5, l = tid & 31;

    if (blockIdx.x < 8) {
        int b = blockIdx.x;
        __shared__ int c[VOCAB];
        c[tid] = 0;
        __syncthreads();
        int P = plen[b];
        #pragma unroll
        for (int it = 0; it < 8; it++) {
            int i = it * 256 + tid;
            int tk = tokens[b * LL + i];
            if (i < P && tk != 0) atomicAdd(&c[tk & 255], 1);
        }
        __syncthreads();
        g_cnt[b * VOCAB + tid] = (float)c[tid];
        return;
    }

    // LN for row v = (blk-8)*8 + w, stored row-major (coalesced float4)
    int v = (blockIdx.x - 8) * 8 + w;
    const float4* E4 = (const float4*)E;
    float4 ef[4];
    #pragma unroll
    for (int j = 0; j < 4; j++) ef[j] = E4[v * 128 + l + 32 * j];
    float s = 0.f;
    #pragma unroll
    for (int j = 0; j < 4; j++) s += ef[j].x + ef[j].y + ef[j].z + ef[j].w;
    float mu = warpSum(s) * (1.f / D);
    float vv = 0.f;
    #pragma unroll
    for (int j = 0; j < 4; j++) {
        ef[j].x -= mu; ef[j].y -= mu; ef[j].z -= mu; ef[j].w -= mu;
        vv += ef[j].x * ef[j].x + ef[j].y * ef[j].y
            + ef[j].z * ef[j].z + ef[j].w * ef[j].w;
    }
    float inv = rsqrtf(warpSum(vv) * (1.f / D) + LN_EPS);
    {
        const float4* G = (const float4*)eg;
        const float4* Bv = (const float4*)eb;
        #pragma unroll
        for (int j = 0; j < 4; j++) {
            float4 g4 = G[l + 32 * j], b4 = Bv[l + 32 * j];
            ef[j].x = ef[j].x * inv * g4.x + b4.x;
            ef[j].y = ef[j].y * inv * g4.y + b4.y;
            ef[j].z = ef[j].z * inv * g4.z + b4.z;
            ef[j].w = ef[j].w * inv * g4.w + b4.w;
        }
    }
    s = 0.f;
    #pragma unroll
    for (int j = 0; j < 4; j++) s += ef[j].x + ef[j].y + ef[j].z + ef[j].w;
    mu = warpSum(s) * (1.f / D);
    vv = 0.f;
    #pragma unroll
    for (int j = 0; j < 4; j++) {
        ef[j].x -= mu; ef[j].y -= mu; ef[j].z -= mu; ef[j].w -= mu;
        vv += ef[j].x * ef[j].x + ef[j].y * ef[j].y
            + ef[j].z * ef[j].z + ef[j].w * ef[j].w;
    }
    inv = rsqrtf(warpSum(vv) * (1.f / D) + LN_EPS);
    {
        const float4* G = (const float4*)fg;
        const float4* Bv = (const float4*)fb;
        #pragma unroll
        for (int j = 0; j < 4; j++) {
            float4 g4 = G[l + 32 * j], b4 = Bv[l + 32 * j];
            float4 hv;
            hv.x = ef[j].x * inv * g4.x + b4.x;
            hv.y = ef[j].y * inv * g4.y + b4.y;
            hv.z = ef[j].z * inv * g4.z + b4.z;
            hv.w = ef[j].w * inv * g4.w + b4.w;
            g_h4[v * 128 + l + 32 * j] = hv;   // row-major, coalesced
        }
    }
}

// ---------------- k_proj: 800 blocks, loads h tile coalesced --------------
// proj block pb: v-rows (pb%32)*8.. , o-cols (pb/32)*16..
// output column o: [0,256) logits, [256,320) q, [320,384) kT, 384 gate
__global__ void __launch_bounds__(256)
k_proj(const float* __restrict__ E,
       const float* __restrict__ qw, const float* __restrict__ qb,
       const float* __restrict__ kw, const float* __restrict__ kb,
       const float* __restrict__ gw, const float* __restrict__ gb) {
    int tid = threadIdx.x, w = tid >> 5, l = tid & 31;
    int pb = blockIdx.x;
    int v0 = (pb & 31) * 8;
    int obase = (pb >> 5) * 16;
    __shared__ __align__(16) float4 hs4[8 * 128];

    // ---- per-warp setup: 2 output columns; weight loads issued first ----
    int olist[2];
    bool oval[2];
    float bias[2];
    const float4* wrow4[2];
    #pragma unroll
    for (int oi = 0; oi < 2; oi++) {
        int o = obase + w * 2 + oi;
        oval[oi] = (o <= 384);
        int oe = oval[oi] ? o : 384;
        olist[oi] = oe;
        const float* wr;
        if (oe < 256)      { wr = E + oe * D;          bias[oi] = 0.f; }
        else if (oe < 320) { wr = qw + (oe - 256) * D; bias[oi] = qb[oe - 256]; }
        else if (oe < 384) { wr = kw + (oe - 320) * D; bias[oi] = kb[oe - 320]; }
        else               { wr = gw;                  bias[oi] = gb[0]; }
        wrow4[oi] = (const float4*)wr;
    }
    float4 e4[2][4];
    #pragma unroll
    for (int oi = 0; oi < 2; oi++)
        #pragma unroll
        for (int jj = 0; jj < 4; jj++)
            e4[oi][jj] = wrow4[oi][l + 32 * jj];

    // ---- h tile: 8 rows, coalesced float4 load from g_h4 ----
    #pragma unroll
    for (int i = 0; i < 4; i++)
        hs4[tid + 256 * i] = g_h4[v0 * 128 + tid + 256 * i];
    __syncthreads();

    // ---- projections: 8 v-rows x 2 o's, register-blocked ----
    float acc[8][2];
    #pragma unroll
    for (int r = 0; r < 8; r++) { acc[r][0] = 0.f; acc[r][1] = 0.f; }

    #pragma unroll
    for (int r = 0; r < 8; r++) {
        #pragma unroll
        for (int jj = 0; jj < 4; jj++) {
            float4 h4 = hs4[r * 128 + l + 32 * jj];
            #pragma unroll
            for (int oi = 0; oi < 2; oi++) {
                acc[r][oi] += e4[oi][jj].x * h4.x + e4[oi][jj].y * h4.y
                            + e4[oi][jj].z * h4.z + e4[oi][jj].w * h4.w;
            }
        }
    }

    // ---- dual reductions: 8 x (5 SHFL) instead of 16 x (5 SHFL) ----
    #pragma unroll
    for (int r = 0; r < 8; r++) {
        float s = warpSumDual(acc[r][0], acc[r][1], l);
        int oi = (l < 16) ? 0 : 1;
        if ((l == 0 || l == 16) && oval[oi]) {
            int o = olist[oi];
            int v = v0 + r;
            if (o < 256)      g_logit[v * VOCAB + o] = s;
            else if (o < 320) g_q[v * A + (o - 256)] = s + bias[oi];
            else if (o < 384) g_kT[(o - 320) * VOCAB + v] = s + bias[oi];
            else              g_gate[v] = 1.f / (1.f + __expf(-(s + bias[oi])));
        }
    }
}

// ---------------- k_sm: vocab softmax + score row per qv ------------------
__global__ void __launch_bounds__(256)
k_sm() {
    int qv = blockIdx.x, tid = threadIdx.x;
    __shared__ float red[8];
    __shared__ float qs[A];
    float lo = g_logit[qv * VOCAB + tid];
    if (tid < A) qs[tid] = g_q[qv * A + tid];
    __syncthreads();                 // qs visible to ALL warps before reading
    float s = 0.f;
    #pragma unroll
    for (int d = 0; d < A; d++) s += qs[d] * g_kT[d * VOCAB + tid];
    g_score[qv * VOCAB + tid] = s * 0.125f;
    float m = blockMax256(lo, red);
    float e = __expf(lo - m);
    float Z = blockSum256(e, red);
    g_vprob[qv * VOCAB + tid] = e * __frcp_rn(Z);
}

// ---------------- k_write: AT/LM compute + streaming writer ---------------
// 256 threads, 16 rows per block, grid (LL/16, BB)
__global__ void __launch_bounds__(256)
k_write(const int* __restrict__ tokens, const int* __restrict__ plen,
        float* __restrict__ out, int has_gate, int has_attn) {
    int b = blockIdx.y, t0 = blockIdx.x * 16, tid = threadIdx.x;
    int w = tid >> 5, l = tid & 31;
    __shared__ __align__(16) int toks[LL];
    __shared__ float lut[16][VOCAB];
    __shared__ float scnt[VOCAB];
    __shared__ int qvs[16];

    scnt[tid] = g_cnt[b * VOCAB + tid];
    const int4* tg = (const int4*)(tokens + b * LL);
    int4* ts = (int4*)toks;
    ts[tid] = tg[tid];
    ts[tid + 256] = tg[tid + 256];
    __syncthreads();
    if (tid < 16) qvs[tid] = toks[t0 + tid] & 255;
    __syncthreads();

    // ---- AT rows: warp w computes rows w and w+8 (shuffles only) ----
    #pragma unroll
    for (int jj = 0; jj < 2; jj++) {
        int j = w + jj * 8;
        int qv = qvs[j];
        float sv[8], cf[8];
        float mx = -1e30f;
        #pragma unroll
        for (int m = 0; m < 8; m++) {
            int v = l + 32 * m;
            sv[m] = g_score[qv * VOCAB + v];
            cf[m] = scnt[v];
            mx = fmaxf(mx, cf[m] > 0.f ? sv[m] : -1e30f);
        }
        mx = warpMax(mx);
        float ex[8], z = 0.f;
        #pragma unroll
        for (int m = 0; m < 8; m++) {
            ex[m] = __expf(sv[m] - mx);
            z += cf[m] * ex[m];
        }
        z = warpSum(z);
        float invz = __frcp_rn(z);
        #pragma unroll
        for (int m = 0; m < 8; m++) {
            int v = l + 32 * m;
            float at = ex[m] * invz;
            if (v == 0) at = 0.f;            // PAD column masked
            lut[j][v] = at;
        }
    }
    __syncthreads();

    int P = plen[b];
    float* out_lm   = out;
    float* out_gate = out + (size_t)BB * LL * VOCAB;
    float* out_attn = out_gate + (size_t)BB * LL;

    if (has_gate && tid < 16) out_gate[b * LL + t0 + tid] = g_gate[qvs[tid]];

    // ---- LM: thread = column, 16 rows ----
    {
        float cn = scnt[tid];
        #pragma unroll
        for (int j = 0; j < 16; j++) {
            int qv = qvs[j];
            float gt = g_gate[qv];
            float pv = g_vprob[qv * VOCAB + tid];
            float mixed = gt * pv + (1.f - gt) * (cn * lut[j][tid]);
            __stcs(out_lm + ((size_t)(b * LL + t0 + j)) * VOCAB + tid,
                   __logf(fmaxf(mixed, 1e-12f)));
        }
    }

    // ---- attn streaming: token loads hoisted, zero-tail does no gather ----
    if (has_attn) {
        int i0 = tid, i1 = 256 + tid;
        int4 tk0 = *(const int4*)&toks[i0 * 4];
        int4 tk1 = *(const int4*)&toks[i1 * 4];
        int a0 = tk0.x & 255, b0 = tk0.y & 255, c0 = tk0.z & 255, d0 = tk0.w & 255;
        int a1 = tk1.x & 255, b1 = tk1.y & 255, c1 = tk1.z & 255, d1 = tk1.w & 255;
        int tfull = P >> 2;           // i < tfull  -> all 4 positions < P
        int tzero = (P + 3) >> 2;     // i >= tzero -> all 4 positions >= P
        bool f0 = i0 < tfull, z0 = i0 >= tzero;
        bool f1 = i1 < tfull, z1 = i1 >= tzero;
        bool m00 = i0 * 4 + 0 < P, m01 = i0 * 4 + 1 < P,
             m02 = i0 * 4 + 2 < P, m03 = i0 * 4 + 3 < P;
        bool m10 = i1 * 4 + 0 < P, m11 = i1 * 4 + 1 < P,
             m12 = i1 * 4 + 2 < P, m13 = i1 * 4 + 3 < P;
        const float4 zero4 = {0.f, 0.f, 0.f, 0.f};

        #pragma unroll
        for (int j = 0; j < 16; j++) {
            const float* L = lut[j];
            float4* orow = (float4*)(out_attn + ((size_t)(b * LL + t0 + j)) * LL);
            float4 o;
            if (f0) {
                o.x = L[a0]; o.y = L[b0]; o.z = L[c0]; o.w = L[d0];
            } else if (z0) {
                o = zero4;
            } else {
                o.x = m00 ? L[a0] : 0.f; o.y = m01 ? L[b0] : 0.f;
                o.z = m02 ? L[c0] : 0.f; o.w = m03 ? L[d0] : 0.f;
            }
            __stcs(orow + i0, o);
            if (f1) {
                o.x = L[a1]; o.y = L[b1]; o.z = L[c1]; o.w = L[d1];
            } else if (z1) {
                o = zero4;
            } else {
                o.x = m10 ? L[a1] : 0.f; o.y = m11 ? L[b1] : 0.f;
                o.z = m12 ? L[c1] : 0.f; o.w = m13 ? L[d1] : 0.f;
            }
            __stcs(orow + i1, o);
        }
    }
}

// ---------------- launch ----------------
extern "C" void kernel_launch(void* const* d_in, const int* in_sizes, int n_in,
                              void* d_out, int out_size) {
    const int*   tokens = (const int*)d_in[0];
    const int*   plen   = (const int*)d_in[1];
    const float* E      = (const float*)d_in[2];
    const float* en_g   = (const float*)d_in[3];
    const float* en_b   = (const float*)d_in[4];
    const float* fn_g   = (const float*)d_in[5];
    const float* fn_b   = (const float*)d_in[6];
    const float* q_w    = (const float*)d_in[7];
    const float* q_b    = (const float*)d_in[8];
    const float* k_w    = (const float*)d_in[9];
    const float* k_b    = (const float*)d_in[10];
    const float* g_w    = (const float*)d_in[11];
    const float* g_b    = (const float*)d_in[12];

    const long long lm_sz   = (long long)BB * LL * VOCAB;
    const long long gate_sz = (long long)BB * LL;
    const long long attn_sz = (long long)BB * LL * LL;
    int has_gate = (out_size >= lm_sz + gate_sz) ? 1 : 0;
    int has_attn = (out_size >= lm_sz + gate_sz + attn_sz) ? 1 : 0;

    k_hn   <<<40, 256>>>(tokens, plen, E, en_g, en_b, fn_g, fn_b);
    k_proj <<<25 * 32, 256>>>(E, q_w, q_b, k_w, k_b, g_w, g_b);
    k_sm   <<<VOCAB, 256>>>();
    k_write<<<dim3(LL / 16, BB), 256>>>(tokens, plen, (float*)d_out, has_gate, has_attn);
}

// round 12
// speedup vs baseline: 1.1231x; 1.1231x over previous
#include <cuda_runtime.h>
#include <cstdint>

#define VOCAB 256
#define D 512
#define A 64
#define BB 8
#define LL 2048
#define LN_EPS 1e-5f
#define LUTW 264   // lut row stride: 256 real cols + sentinel(256)=0 + pad

// ---------------- scratch (device globals; no allocations) ----------------
__device__ float4 g_h4[VOCAB * 128];       // h row-major: [v][d/4]
__device__ float g_q[VOCAB * A];
__device__ float g_kT[A * VOCAB];
__device__ float g_gate[VOCAB];
__device__ float g_logit[VOCAB * VOCAB];
__device__ float g_vprob[VOCAB * VOCAB];
__device__ float g_score[VOCAB * VOCAB];
__device__ float g_cnt[BB * VOCAB];

// ---------------- reduction helpers ----------------
__device__ __forceinline__ float warpSum(float v) {
    #pragma unroll
    for (int o = 16; o > 0; o >>= 1) v += __shfl_xor_sync(0xFFFFFFFFu, v, o);
    return v;
}
__device__ __forceinline__ float warpMax(float v) {
    #pragma unroll
    for (int o = 16; o > 0; o >>= 1) v = fmaxf(v, __shfl_xor_sync(0xFFFFFFFFu, v, o));
    return v;
}
__device__ __forceinline__ float blockSum256(float v, float* sh) {
    int w = threadIdx.x >> 5, l = threadIdx.x & 31;
    v = warpSum(v);
    if (l == 0) sh[w] = v;
    __syncthreads();
    if (w == 0) {
        float x = (l < 8) ? sh[l] : 0.f;
        x = warpSum(x);
        if (l == 0) sh[0] = x;
    }
    __syncthreads();
    float r = sh[0];
    __syncthreads();
    return r;
}
__device__ __forceinline__ float blockMax256(float v, float* sh) {
    int w = threadIdx.x >> 5, l = threadIdx.x & 31;
    v = warpMax(v);
    if (l == 0) sh[w] = v;
    __syncthreads();
    if (w == 0) {
        float x = (l < 8) ? sh[l] : -1e30f;
        x = warpMax(x);
        if (l == 0) sh[0] = x;
    }
    __syncthreads();
    float r = sh[0];
    __syncthreads();
    return r;
}

// ---------------- k_hn: histogram (blocks 0-7) + LN once (blocks 8-39) ----
__global__ void __launch_bounds__(256)
k_hn(const int* __restrict__ tokens, const int* __restrict__ plen,
     const float* __restrict__ E,
     const float* __restrict__ eg, const float* __restrict__ eb,
     const float* __restrict__ fg, const float* __restrict__ fb) {
    int tid = threadIdx.x, w = tid >> 5, l = tid & 31;

    if (blockIdx.x < 8) {
        int b = blockIdx.x;
        __shared__ int c[VOCAB];
        c[tid] = 0;
        __syncthreads();
        int P = plen[b];
        #pragma unroll
        for (int it = 0; it < 8; it++) {
            int i = it * 256 + tid;
            int tk = tokens[b * LL + i];
            if (i < P && tk != 0) atomicAdd(&c[tk & 255], 1);
        }
        __syncthreads();
        g_cnt[b * VOCAB + tid] = (float)c[tid];
        return;
    }

    // LN for row v = (blk-8)*8 + w, stored row-major (coalesced float4)
    int v = (blockIdx.x - 8) * 8 + w;
    const float4* E4 = (const float4*)E;
    float4 ef[4];
    #pragma unroll
    for (int j = 0; j < 4; j++) ef[j] = E4[v * 128 + l + 32 * j];
    float s = 0.f;
    #pragma unroll
    for (int j = 0; j < 4; j++) s += ef[j].x + ef[j].y + ef[j].z + ef[j].w;
    float mu = warpSum(s) * (1.f / D);
    float vv = 0.f;
    #pragma unroll
    for (int j = 0; j < 4; j++) {
        ef[j].x -= mu; ef[j].y -= mu; ef[j].z -= mu; ef[j].w -= mu;
        vv += ef[j].x * ef[j].x + ef[j].y * ef[j].y
            + ef[j].z * ef[j].z + ef[j].w * ef[j].w;
    }
    float inv = rsqrtf(warpSum(vv) * (1.f / D) + LN_EPS);
    {
        const float4* G = (const float4*)eg;
        const float4* Bv = (const float4*)eb;
        #pragma unroll
        for (int j = 0; j < 4; j++) {
            float4 g4 = G[l + 32 * j], b4 = Bv[l + 32 * j];
            ef[j].x = ef[j].x * inv * g4.x + b4.x;
            ef[j].y = ef[j].y * inv * g4.y + b4.y;
            ef[j].z = ef[j].z * inv * g4.z + b4.z;
            ef[j].w = ef[j].w * inv * g4.w + b4.w;
        }
    }
    s = 0.f;
    #pragma unroll
    for (int j = 0; j < 4; j++) s += ef[j].x + ef[j].y + ef[j].z + ef[j].w;
    mu = warpSum(s) * (1.f / D);
    vv = 0.f;
    #pragma unroll
    for (int j = 0; j < 4; j++) {
        ef[j].x -= mu; ef[j].y -= mu; ef[j].z -= mu; ef[j].w -= mu;
        vv += ef[j].x * ef[j].x + ef[j].y * ef[j].y
            + ef[j].z * ef[j].z + ef[j].w * ef[j].w;
    }
    inv = rsqrtf(warpSum(vv) * (1.f / D) + LN_EPS);
    {
        const float4* G = (const float4*)fg;
        const float4* Bv = (const float4*)fb;
        #pragma unroll
        for (int j = 0; j < 4; j++) {
            float4 g4 = G[l + 32 * j], b4 = Bv[l + 32 * j];
            float4 hv;
            hv.x = ef[j].x * inv * g4.x + b4.x;
            hv.y = ef[j].y * inv * g4.y + b4.y;
            hv.z = ef[j].z * inv * g4.z + b4.z;
            hv.w = ef[j].w * inv * g4.w + b4.w;
            g_h4[v * 128 + l + 32 * j] = hv;   // row-major, coalesced
        }
    }
}

// ---------------- k_proj: 800 blocks, loads h tile coalesced --------------
// proj block pb: v-rows (pb%32)*8.. , o-cols (pb/32)*16..
// output column o: [0,256) logits, [256,320) q, [320,384) kT, 384 gate
__global__ void __launch_bounds__(256)
k_proj(const float* __restrict__ E,
       const float* __restrict__ qw, const float* __restrict__ qb,
       const float* __restrict__ kw, const float* __restrict__ kb,
       const float* __restrict__ gw, const float* __restrict__ gb) {
    int tid = threadIdx.x, w = tid >> 5, l = tid & 31;
    int pb = blockIdx.x;
    int v0 = (pb & 31) * 8;
    int obase = (pb >> 5) * 16;
    __shared__ __align__(16) float4 hs4[8 * 128];

    // ---- per-warp setup: 2 output columns; weight loads issued first ----
    int olist[2];
    bool oval[2];
    float bias[2];
    const float4* wrow4[2];
    #pragma unroll
    for (int oi = 0; oi < 2; oi++) {
        int o = obase + w * 2 + oi;
        oval[oi] = (o <= 384);
        int oe = oval[oi] ? o : 384;
        olist[oi] = oe;
        const float* wr;
        if (oe < 256)      { wr = E + oe * D;          bias[oi] = 0.f; }
        else if (oe < 320) { wr = qw + (oe - 256) * D; bias[oi] = qb[oe - 256]; }
        else if (oe < 384) { wr = kw + (oe - 320) * D; bias[oi] = kb[oe - 320]; }
        else               { wr = gw;                  bias[oi] = gb[0]; }
        wrow4[oi] = (const float4*)wr;
    }
    float4 e4[2][4];
    #pragma unroll
    for (int oi = 0; oi < 2; oi++)
        #pragma unroll
        for (int jj = 0; jj < 4; jj++)
            e4[oi][jj] = wrow4[oi][l + 32 * jj];

    // ---- h tile: 8 rows, coalesced float4 load from g_h4 ----
    #pragma unroll
    for (int i = 0; i < 4; i++)
        hs4[tid + 256 * i] = g_h4[v0 * 128 + tid + 256 * i];
    __syncthreads();

    // ---- projections: 8 v-rows x 2 o's, register-blocked ----
    float acc[8][2];
    #pragma unroll
    for (int r = 0; r < 8; r++) { acc[r][0] = 0.f; acc[r][1] = 0.f; }

    #pragma unroll
    for (int r = 0; r < 8; r++) {
        #pragma unroll
        for (int jj = 0; jj < 4; jj++) {
            float4 h4 = hs4[r * 128 + l + 32 * jj];
            #pragma unroll
            for (int oi = 0; oi < 2; oi++) {
                acc[r][oi] += e4[oi][jj].x * h4.x + e4[oi][jj].y * h4.y
                            + e4[oi][jj].z * h4.z + e4[oi][jj].w * h4.w;
            }
        }
    }

    #pragma unroll
    for (int oi = 0; oi < 2; oi++) {
        #pragma unroll
        for (int r = 0; r < 8; r++) {
            float s = warpSum(acc[r][oi]);
            if (l == 0 && oval[oi]) {
                int o = olist[oi];
                int v = v0 + r;
                if (o < 256)      g_logit[v * VOCAB + o] = s;
                else if (o < 320) g_q[v * A + (o - 256)] = s + bias[oi];
                else if (o < 384) g_kT[(o - 320) * VOCAB + v] = s + bias[oi];
                else              g_gate[v] = 1.f / (1.f + __expf(-(s + bias[oi])));
            }
        }
    }
}

// ---------------- k_sm: vocab softmax + score row per qv ------------------
__global__ void __launch_bounds__(256)
k_sm() {
    int qv = blockIdx.x, tid = threadIdx.x;
    __shared__ float red[8];
    __shared__ float qs[A];
    float lo = g_logit[qv * VOCAB + tid];
    if (tid < A) qs[tid] = g_q[qv * A + tid];
    __syncthreads();                 // qs visible to ALL warps before reading
    float s = 0.f;
    #pragma unroll
    for (int d = 0; d < A; d++) s += qs[d] * g_kT[d * VOCAB + tid];
    g_score[qv * VOCAB + tid] = s * 0.125f;
    float m = blockMax256(lo, red);
    float e = __expf(lo - m);
    float Z = blockSum256(e, red);
    g_vprob[qv * VOCAB + tid] = e * __frcp_rn(Z);
}

// ---------------- k_write: AT/LM compute + branch-free streaming writer ---
// 256 threads, 16 rows per block, grid (LL/16, BB)
// tokens staged in smem CLAMPED: positions >= P get sentinel value 256;
// lut[j][256] = 0 -> the gather loop needs no masks at all.
__global__ void __launch_bounds__(256)
k_write(const int* __restrict__ tokens, const int* __restrict__ plen,
        float* __restrict__ out, int has_gate, int has_attn) {
    int b = blockIdx.y, t0 = blockIdx.x * 16, tid = threadIdx.x;
    int w = tid >> 5, l = tid & 31;
    __shared__ __align__(16) int toks[LL];       // clamped tokens
    __shared__ float lut[16][LUTW];
    __shared__ float scnt[VOCAB];
    __shared__ int qvs[16];

    int P = plen[b];
    scnt[tid] = g_cnt[b * VOCAB + tid];
    if (tid < 16) qvs[tid] = tokens[b * LL + t0 + tid] & 255;   // RAW query tokens
    const int4* tg = (const int4*)(tokens + b * LL);
    int4* ts = (int4*)toks;
    #pragma unroll
    for (int h = 0; h < 2; h++) {
        int idx = tid + 256 * h;
        int4 t4 = tg[idx];
        int base = idx * 4;
        t4.x = (base + 0 < P) ? (t4.x & 255) : 256;
        t4.y = (base + 1 < P) ? (t4.y & 255) : 256;
        t4.z = (base + 2 < P) ? (t4.z & 255) : 256;
        t4.w = (base + 3 < P) ? (t4.w & 255) : 256;
        ts[idx] = t4;
    }
    __syncthreads();

    // ---- AT rows: warp w computes rows w and w+8 (shuffles only) ----
    #pragma unroll
    for (int jj = 0; jj < 2; jj++) {
        int j = w + jj * 8;
        int qv = qvs[j];
        float sv[8], cf[8];
        float mx = -1e30f;
        #pragma unroll
        for (int m = 0; m < 8; m++) {
            int v = l + 32 * m;
            sv[m] = g_score[qv * VOCAB + v];
            cf[m] = scnt[v];
            mx = fmaxf(mx, cf[m] > 0.f ? sv[m] : -1e30f);
        }
        mx = warpMax(mx);
        float ex[8], z = 0.f;
        #pragma unroll
        for (int m = 0; m < 8; m++) {
            ex[m] = __expf(sv[m] - mx);
            z += cf[m] * ex[m];
        }
        z = warpSum(z);
        float invz = __frcp_rn(z);
        #pragma unroll
        for (int m = 0; m < 8; m++) {
            int v = l + 32 * m;
            float at = ex[m] * invz;
            if (v == 0) at = 0.f;            // PAD column masked
            lut[j][v] = at;
        }
        if (l == 0) lut[j][256] = 0.f;       // sentinel for s >= P
    }
    __syncthreads();

    float* out_lm   = out;
    float* out_gate = out + (size_t)BB * LL * VOCAB;
    float* out_attn = out_gate + (size_t)BB * LL;

    if (has_gate && tid < 16) out_gate[b * LL + t0 + tid] = g_gate[qvs[tid]];

    // ---- LM: thread = column, 16 rows ----
    {
        float cn = scnt[tid];
        #pragma unroll
        for (int j = 0; j < 16; j++) {
            int qv = qvs[j];
            float gt = g_gate[qv];
            float pv = g_vprob[qv * VOCAB + tid];
            float mixed = gt * pv + (1.f - gt) * (cn * lut[j][tid]);
            __stcs(out_lm + ((size_t)(b * LL + t0 + j)) * VOCAB + tid,
                   __logf(fmaxf(mixed, 1e-12f)));
        }
    }

    // ---- attn streaming: branch-free, mask-free gather ----
    if (has_attn) {
        int4 tk0 = ts[tid];
        int4 tk1 = ts[tid + 256];
        #pragma unroll
        for (int j = 0; j < 16; j++) {
            const float* L = lut[j];
            float4* orow = (float4*)(out_attn + ((size_t)(b * LL + t0 + j)) * LL);
            float4 o;
            o.x = L[tk0.x]; o.y = L[tk0.y]; o.z = L[tk0.z]; o.w = L[tk0.w];
            __stcs(orow + tid, o);
            o.x = L[tk1.x]; o.y = L[tk1.y]; o.z = L[tk1.z]; o.w = L[tk1.w];
            __stcs(orow + 256 + tid, o);
        }
    }
}

// ---------------- launch ----------------
extern "C" void kernel_launch(void* const* d_in, const int* in_sizes, int n_in,
                              void* d_out, int out_size) {
    const int*   tokens = (const int*)d_in[0];
    const int*   plen   = (const int*)d_in[1];
    const float* E      = (const float*)d_in[2];
    const float* en_g   = (const float*)d_in[3];
    const float* en_b   = (const float*)d_in[4];
    const float* fn_g   = (const float*)d_in[5];
    const float* fn_b   = (const float*)d_in[6];
    const float* q_w    = (const float*)d_in[7];
    const float* q_b    = (const float*)d_in[8];
    const float* k_w    = (const float*)d_in[9];
    const float* k_b    = (const float*)d_in[10];
    const float* g_w    = (const float*)d_in[11];
    const float* g_b    = (const float*)d_in[12];

    const long long lm_sz   = (long long)BB * LL * VOCAB;
    const long long gate_sz = (long long)BB * LL;
    const long long attn_sz = (long long)BB * LL * LL;
    int has_gate = (out_size >= lm_sz + gate_sz) ? 1 : 0;
    int has_attn = (out_size >= lm_sz + gate_sz + attn_sz) ? 1 : 0;

    k_hn   <<<40, 256>>>(tokens, plen, E, en_g, en_b, fn_g, fn_b);
    k_proj <<<25 * 32, 256>>>(E, q_w, q_b, k_w, k_b, g_w, g_b);
    k_sm   <<<VOCAB, 256>>>();
    k_write<<<dim3(LL / 16, BB), 256>>>(tokens, plen, (float*)d_out, has_gate, has_attn);
}